// round 10
// baseline (speedup 1.0000x reference)
#include <cuda_runtime.h>
#include <cuda_bf16.h>
#include <math.h>

// Shapes (fixed dataset):
//   x_all: [100000, 256] f32, n_id: [50000] i32, edge_index: [2, 300000] i32
//   W_sage: [256,256] f32, b_sage: [256] f32, W_cls: [3,256] f32, b_cls: [3] f32
//   out: [50000, 3] f32 (log_softmax)
//
// out = log_softmax( mean_j( x[j] @ Wc ) + bc )  (linearity)
// 3-kernel PDL pipeline:
//   k_init (weight fusion) -> k_z (project, heavy load pre-wait) ->
//   k_ef   (edge REDG + internal grid barrier + finalize, one kernel)
#define NMAX 50000
#define FDIM 256
#define F4   64
#define CCLS 3

__device__ float  g_Wc [CCLS * FDIM];
__device__ float  g_bc [CCLS];
__device__ float4 g_z  [NMAX];
__device__ float4 g_acc[NMAX];

// sense-reversal barrier state for k_ef (gen monotone across graph replays)
__device__ unsigned g_done = 0;
__device__ unsigned g_rel  = 0;

__device__ __forceinline__ void pdl_wait()    { asm volatile("griddepcontrol.wait;" ::: "memory"); }
__device__ __forceinline__ void pdl_trigger() { asm volatile("griddepcontrol.launch_dependents;" ::: "memory"); }
__device__ __forceinline__ void redg_v4(float4* p, float4 v) {
    asm volatile("red.global.add.v4.f32 [%0], {%1, %2, %3, %4};"
                 :: "l"(p), "f"(v.x), "f"(v.y), "f"(v.z), "f"(v.w) : "memory");
}

// ---------------------------------------------------------------------------
// Kernel 0: parallel weight fusion. One warp per output element.
// ---------------------------------------------------------------------------
__global__ void k_init(const float* __restrict__ W_sage,
                       const float* __restrict__ b_sage,
                       const float* __restrict__ W_cls,
                       const float* __restrict__ b_cls) {
    int gid  = blockIdx.x * blockDim.x + threadIdx.x;
    int ww   = gid >> 5;
    int lane = gid & 31;
    const unsigned full = 0xffffffffu;

    if (ww < CCLS * FDIM) {
        int c = ww >> 8;
        int k = ww & 255;
        const float4* wrow = reinterpret_cast<const float4*>(W_sage + k * FDIM);
        const float4* crow = reinterpret_cast<const float4*>(W_cls  + c * FDIM);
        float4 a0 = __ldg(&wrow[lane]);      float4 b0 = __ldg(&crow[lane]);
        float4 a1 = __ldg(&wrow[lane + 32]); float4 b1 = __ldg(&crow[lane + 32]);
        float s = fmaf(a0.x, b0.x, fmaf(a0.y, b0.y, fmaf(a0.z, b0.z, a0.w * b0.w)))
                + fmaf(a1.x, b1.x, fmaf(a1.y, b1.y, fmaf(a1.z, b1.z, a1.w * b1.w)));
        #pragma unroll
        for (int off = 16; off > 0; off >>= 1)
            s += __shfl_down_sync(full, s, off);
        if (lane == 0) g_Wc[c * FDIM + k] = s;
    } else if (ww < CCLS * FDIM + CCLS) {
        int c = ww - CCLS * FDIM;
        const float4* brow = reinterpret_cast<const float4*>(b_sage);
        const float4* crow = reinterpret_cast<const float4*>(W_cls + c * FDIM);
        float4 a0 = __ldg(&brow[lane]);      float4 b0 = __ldg(&crow[lane]);
        float4 a1 = __ldg(&brow[lane + 32]); float4 b1 = __ldg(&crow[lane + 32]);
        float s = fmaf(a0.x, b0.x, fmaf(a0.y, b0.y, fmaf(a0.z, b0.z, a0.w * b0.w)))
                + fmaf(a1.x, b1.x, fmaf(a1.y, b1.y, fmaf(a1.z, b1.z, a1.w * b1.w)));
        #pragma unroll
        for (int off = 16; off > 0; off >>= 1)
            s += __shfl_down_sync(full, s, off);
        if (lane == 0) g_bc[c] = s + __ldg(&b_cls[c]);
    }
    pdl_trigger();
}

// ---------------------------------------------------------------------------
// Kernel 1: project. One warp per node: z[i] = x_all[n_id[i]] @ Wc, .w = 1.
// The 51MB row fetch is PRE-wait (overlaps k_init fully).
// ---------------------------------------------------------------------------
__global__ void k_z(const float4* __restrict__ x_all4,
                    const int* __restrict__ n_id, int N) {
    __shared__ float sW[CCLS][FDIM];
    int t    = threadIdx.x;
    int w    = (blockIdx.x * blockDim.x + t) >> 5;
    int lane = t & 31;

    float4 a0 = make_float4(0.f, 0.f, 0.f, 0.f), a1 = a0;
    if (w < N) {
        int row = __ldg(&n_id[w]);
        const float4* xp = x_all4 + (long long)row * F4;
        a0 = __ldg(&xp[lane]);
        a1 = __ldg(&xp[lane + 32]);
    }

    pdl_wait();   // g_Wc ready
    for (int idx = t; idx < CCLS * FDIM; idx += blockDim.x)
        sW[idx >> 8][idx & 255] = g_Wc[idx];
    __syncthreads();

    if (w < N) {
        int k0 = lane * 4, k1 = (lane + 32) * 4;
        float s0, s1, s2;
        {
            float t0, t1, t2;
            t0 = fmaf(a0.x, sW[0][k0], fmaf(a0.y, sW[0][k0+1], fmaf(a0.z, sW[0][k0+2], a0.w * sW[0][k0+3])));
            t1 = fmaf(a0.x, sW[1][k0], fmaf(a0.y, sW[1][k0+1], fmaf(a0.z, sW[1][k0+2], a0.w * sW[1][k0+3])));
            t2 = fmaf(a0.x, sW[2][k0], fmaf(a0.y, sW[2][k0+1], fmaf(a0.z, sW[2][k0+2], a0.w * sW[2][k0+3])));
            s0 = fmaf(a1.x, sW[0][k1], fmaf(a1.y, sW[0][k1+1], fmaf(a1.z, sW[0][k1+2], fmaf(a1.w, sW[0][k1+3], t0))));
            s1 = fmaf(a1.x, sW[1][k1], fmaf(a1.y, sW[1][k1+1], fmaf(a1.z, sW[1][k1+2], fmaf(a1.w, sW[1][k1+3], t1))));
            s2 = fmaf(a1.x, sW[2][k1], fmaf(a1.y, sW[2][k1+1], fmaf(a1.z, sW[2][k1+2], fmaf(a1.w, sW[2][k1+3], t2))));
        }
        const unsigned full = 0xffffffffu;
        #pragma unroll
        for (int off = 16; off > 0; off >>= 1) {
            s0 += __shfl_down_sync(full, s0, off);
            s1 += __shfl_down_sync(full, s1, off);
            s2 += __shfl_down_sync(full, s2, off);
        }
        if (lane == 0) {
            float4 zv = make_float4(s0, s1, s2, 1.0f);
            g_z[w]   = zv;
            g_acc[w] = zv;   // self loop (+count)
        }
    }
    pdl_trigger();
}

// ---------------------------------------------------------------------------
// Kernel 2: edges + finalize in ONE kernel.
//   phase A: 8 edges/thread, v4 REDG into g_acc
//   internal sense-reversal barrier (147 blocks, <=1/SM: co-resident; its
//   blocks never wait on other kernels -> no deadlock)
//   phase B: grid-stride finalize (mean + bias + log_softmax)
// ---------------------------------------------------------------------------
__global__ void __launch_bounds__(256, 2)
k_ef(const int* __restrict__ src, const int* __restrict__ dst,
     float* __restrict__ out, int E, int N) {
    __shared__ unsigned s_gen;
    int t   = threadIdx.x;
    int tid = blockIdx.x * blockDim.x + t;

    // pre-wait prologue: barrier generation + edge indices (kernel inputs)
    if (t == 0) s_gen = *(volatile unsigned*)&g_rel;   // before our increment -> safe
    int e0 = tid * 8;
    int4 sa, sb, da, db;
    bool fullquad = (e0 + 7 < E);
    if (fullquad) {
        sa = __ldg(reinterpret_cast<const int4*>(src) + tid * 2);
        sb = __ldg(reinterpret_cast<const int4*>(src) + tid * 2 + 1);
        da = __ldg(reinterpret_cast<const int4*>(dst) + tid * 2);
        db = __ldg(reinterpret_cast<const int4*>(dst) + tid * 2 + 1);
    }

    pdl_wait();   // g_z / g_acc (and transitively g_bc) ready

    // ---- phase A: edge aggregation ----------------------------------------
    if (fullquad) {
        float4 v0 = __ldg(&g_z[sa.x]);
        float4 v1 = __ldg(&g_z[sa.y]);
        float4 v2 = __ldg(&g_z[sa.z]);
        float4 v3 = __ldg(&g_z[sa.w]);
        float4 v4 = __ldg(&g_z[sb.x]);
        float4 v5 = __ldg(&g_z[sb.y]);
        float4 v6 = __ldg(&g_z[sb.z]);
        float4 v7 = __ldg(&g_z[sb.w]);
        redg_v4(&g_acc[da.x], v0);
        redg_v4(&g_acc[da.y], v1);
        redg_v4(&g_acc[da.z], v2);
        redg_v4(&g_acc[da.w], v3);
        redg_v4(&g_acc[db.x], v4);
        redg_v4(&g_acc[db.y], v5);
        redg_v4(&g_acc[db.z], v6);
        redg_v4(&g_acc[db.w], v7);
    } else {
        for (int e = e0; e < E; e++) {
            int s = __ldg(&src[e]);
            int d = __ldg(&dst[e]);
            redg_v4(&g_acc[d], __ldg(&g_z[s]));
        }
    }

    // ---- internal grid barrier -------------------------------------------
    __threadfence();        // push REDGs toward L2 ordering point
    __syncthreads();
    if (t == 0) {
        unsigned target = s_gen + 1;
        if (atomicAdd(&g_done, 1u) == gridDim.x - 1) {
            g_done = 0;
            __threadfence();
            atomicExch(&g_rel, target);           // release
        } else {
            while (*(volatile unsigned*)&g_rel != target) __nanosleep(20);
        }
        __threadfence();                          // acquire
    }
    __syncthreads();

    // ---- phase B: finalize ------------------------------------------------
    float bc0 = g_bc[0], bc1 = g_bc[1], bc2 = g_bc[2];
    int stride = gridDim.x * blockDim.x;
    for (int i = tid; i < N; i += stride) {
        float4 a = g_acc[i];
        float inv = __frcp_rn(a.w);
        float s0 = fmaf(a.x, inv, bc0);
        float s1 = fmaf(a.y, inv, bc1);
        float s2 = fmaf(a.z, inv, bc2);
        float m   = fmaxf(s0, fmaxf(s1, s2));
        float e0f = __expf(s0 - m);
        float e1f = __expf(s1 - m);
        float e2f = __expf(s2 - m);
        float lse = m + __logf(e0f + e1f + e2f);
        out[i * 3 + 0] = s0 - lse;
        out[i * 3 + 1] = s1 - lse;
        out[i * 3 + 2] = s2 - lse;
    }
}

// ---------------------------------------------------------------------------
static inline void launch_pdl(void* fn, dim3 grid, dim3 block,
                              void** args, bool pdl_in) {
    cudaLaunchConfig_t cfg = {};
    cfg.gridDim  = grid;
    cfg.blockDim = block;
    cfg.dynamicSmemBytes = 0;
    cfg.stream = 0;
    cudaLaunchAttribute attr[1];
    int nattr = 0;
    if (pdl_in) {
        attr[0].id = cudaLaunchAttributeProgrammaticStreamSerialization;
        attr[0].val.programmaticStreamSerializationAllowed = 1;
        nattr = 1;
    }
    cfg.attrs = attr;
    cfg.numAttrs = nattr;
    cudaLaunchKernelExC(&cfg, fn, args);
}

extern "C" void kernel_launch(void* const* d_in, const int* in_sizes, int n_in,
                              void* d_out, int out_size) {
    const float* x_all  = (const float*)d_in[0];
    const int*   n_id   = (const int*)  d_in[1];
    const int*   eidx   = (const int*)  d_in[2];
    const float* W_sage = (const float*)d_in[3];
    const float* b_sage = (const float*)d_in[4];
    const float* W_cls  = (const float*)d_in[5];
    const float* b_cls  = (const float*)d_in[6];
    float* out = (float*)d_out;

    int N = in_sizes[1];          // 50000
    int E = in_sizes[2] / 2;      // 300000
    const int* src = eidx;        // edge_index[0, :]
    const int* dst = eidx + E;    // edge_index[1, :]

    // k_init: 771 warp-tasks
    {
        int threads = (CCLS * FDIM + CCLS) * 32;
        dim3 g((threads + 255) / 256), b(256);
        void* args[] = {(void*)&W_sage, (void*)&b_sage, (void*)&W_cls, (void*)&b_cls};
        launch_pdl((void*)k_init, g, b, args, false);
    }
    // k_z: one warp per node
    {
        const float4* x4 = reinterpret_cast<const float4*>(x_all);
        long long th = (long long)N * 32;
        dim3 g((unsigned)((th + 255) / 256)), b(256);
        void* args[] = {(void*)&x4, (void*)&n_id, (void*)&N};
        launch_pdl((void*)k_z, g, b, args, true);
    }
    // k_ef: 8 edges/thread -> 147 blocks (<= 1/SM), edges + barrier + finalize
    {
        int threads = (E + 7) / 8;
        dim3 g((threads + 255) / 256), b(256);
        void* args[] = {(void*)&src, (void*)&dst, (void*)&out, (void*)&E, (void*)&N};
        launch_pdl((void*)k_ef, g, b, args, true);
    }
}

// round 11
// speedup vs baseline: 1.2076x; 1.2076x over previous
#include <cuda_runtime.h>
#include <cuda_bf16.h>
#include <math.h>

// Shapes (fixed dataset):
//   x_all: [100000, 256] f32, n_id: [50000] i32, edge_index: [2, 300000] i32
//   W_sage: [256,256] f32, b_sage: [256] f32, W_cls: [3,256] f32, b_cls: [3] f32
//   out: [50000, 3] f32 (log_softmax)
//
// out = log_softmax( mean_j( x[j] @ Wc ) + bc )  (linearity)
// 4-kernel PDL pipeline (R8 structure): k_init -> k_z -> k_edge -> k_final
// R11 change: k_z does TWO nodes per warp (4 independent LDG.128/lane in
// flight instead of 2) to cut exposed memory latency.
#define NMAX 50000
#define FDIM 256
#define F4   64
#define CCLS 3

__device__ float  g_Wc [CCLS * FDIM];
__device__ float  g_bc [CCLS];
__device__ float4 g_z  [NMAX];
__device__ float4 g_acc[NMAX];

__device__ __forceinline__ void pdl_wait()    { asm volatile("griddepcontrol.wait;" ::: "memory"); }
__device__ __forceinline__ void pdl_trigger() { asm volatile("griddepcontrol.launch_dependents;" ::: "memory"); }
__device__ __forceinline__ void redg_v4(float4* p, float4 v) {
    asm volatile("red.global.add.v4.f32 [%0], {%1, %2, %3, %4};"
                 :: "l"(p), "f"(v.x), "f"(v.y), "f"(v.z), "f"(v.w) : "memory");
}

// ---------------------------------------------------------------------------
// Kernel 0: parallel weight fusion. One warp per output element.
// ---------------------------------------------------------------------------
__global__ void k_init(const float* __restrict__ W_sage,
                       const float* __restrict__ b_sage,
                       const float* __restrict__ W_cls,
                       const float* __restrict__ b_cls) {
    int gid  = blockIdx.x * blockDim.x + threadIdx.x;
    int ww   = gid >> 5;
    int lane = gid & 31;
    const unsigned full = 0xffffffffu;

    if (ww < CCLS * FDIM) {
        int c = ww >> 8;
        int k = ww & 255;
        const float4* wrow = reinterpret_cast<const float4*>(W_sage + k * FDIM);
        const float4* crow = reinterpret_cast<const float4*>(W_cls  + c * FDIM);
        float4 a0 = __ldg(&wrow[lane]);      float4 b0 = __ldg(&crow[lane]);
        float4 a1 = __ldg(&wrow[lane + 32]); float4 b1 = __ldg(&crow[lane + 32]);
        float s = fmaf(a0.x, b0.x, fmaf(a0.y, b0.y, fmaf(a0.z, b0.z, a0.w * b0.w)))
                + fmaf(a1.x, b1.x, fmaf(a1.y, b1.y, fmaf(a1.z, b1.z, a1.w * b1.w)));
        #pragma unroll
        for (int off = 16; off > 0; off >>= 1)
            s += __shfl_down_sync(full, s, off);
        if (lane == 0) g_Wc[c * FDIM + k] = s;
    } else if (ww < CCLS * FDIM + CCLS) {
        int c = ww - CCLS * FDIM;
        const float4* brow = reinterpret_cast<const float4*>(b_sage);
        const float4* crow = reinterpret_cast<const float4*>(W_cls + c * FDIM);
        float4 a0 = __ldg(&brow[lane]);      float4 b0 = __ldg(&crow[lane]);
        float4 a1 = __ldg(&brow[lane + 32]); float4 b1 = __ldg(&crow[lane + 32]);
        float s = fmaf(a0.x, b0.x, fmaf(a0.y, b0.y, fmaf(a0.z, b0.z, a0.w * b0.w)))
                + fmaf(a1.x, b1.x, fmaf(a1.y, b1.y, fmaf(a1.z, b1.z, a1.w * b1.w)));
        #pragma unroll
        for (int off = 16; off > 0; off >>= 1)
            s += __shfl_down_sync(full, s, off);
        if (lane == 0) g_bc[c] = s + __ldg(&b_cls[c]);
    }
    pdl_trigger();
}

// ---------------------------------------------------------------------------
// Kernel 1: project, TWO nodes per warp.
//   z[i] = x_all[n_id[i]] @ Wc, .w = 1;  acc[i] = z[i]  (self loop)
// Row fetches (4 independent LDG.128/lane) are PRE-wait prologue.
// ---------------------------------------------------------------------------
__global__ void k_z(const float4* __restrict__ x_all4,
                    const int* __restrict__ n_id, int N) {
    __shared__ float sW[CCLS][FDIM];
    int t    = threadIdx.x;
    int wp   = (blockIdx.x * blockDim.x + t) >> 5;   // warp id
    int lane = t & 31;
    int w0 = wp * 2;
    int w1 = w0 + 1;
    bool h0 = (w0 < N), h1 = (w1 < N);

    float4 a0 = make_float4(0.f,0.f,0.f,0.f), a1 = a0, c0 = a0, c1 = a0;
    if (h0) {
        int row = __ldg(&n_id[w0]);
        const float4* xp = x_all4 + (long long)row * F4;
        a0 = __ldg(&xp[lane]);
        a1 = __ldg(&xp[lane + 32]);
    }
    if (h1) {
        int row = __ldg(&n_id[w1]);
        const float4* xp = x_all4 + (long long)row * F4;
        c0 = __ldg(&xp[lane]);
        c1 = __ldg(&xp[lane + 32]);
    }

    pdl_wait();   // g_Wc ready
    for (int idx = t; idx < CCLS * FDIM; idx += blockDim.x)
        sW[idx >> 8][idx & 255] = g_Wc[idx];
    __syncthreads();

    if (!h0) { pdl_trigger(); return; }

    int k0 = lane * 4, k1 = (lane + 32) * 4;
    float w00 = sW[0][k0], w01 = sW[0][k0+1], w02 = sW[0][k0+2], w03 = sW[0][k0+3];
    float w10 = sW[1][k0], w11 = sW[1][k0+1], w12 = sW[1][k0+2], w13 = sW[1][k0+3];
    float w20 = sW[2][k0], w21 = sW[2][k0+1], w22 = sW[2][k0+2], w23 = sW[2][k0+3];
    float v00 = sW[0][k1], v01 = sW[0][k1+1], v02 = sW[0][k1+2], v03 = sW[0][k1+3];
    float v10 = sW[1][k1], v11 = sW[1][k1+1], v12 = sW[1][k1+2], v13 = sW[1][k1+3];
    float v20 = sW[2][k1], v21 = sW[2][k1+1], v22 = sW[2][k1+2], v23 = sW[2][k1+3];

    // node 0 dots
    float x0 = fmaf(a0.x,w00, fmaf(a0.y,w01, fmaf(a0.z,w02, a0.w*w03)));
    float x1 = fmaf(a0.x,w10, fmaf(a0.y,w11, fmaf(a0.z,w12, a0.w*w13)));
    float x2 = fmaf(a0.x,w20, fmaf(a0.y,w21, fmaf(a0.z,w22, a0.w*w23)));
    x0 = fmaf(a1.x,v00, fmaf(a1.y,v01, fmaf(a1.z,v02, fmaf(a1.w,v03, x0))));
    x1 = fmaf(a1.x,v10, fmaf(a1.y,v11, fmaf(a1.z,v12, fmaf(a1.w,v13, x1))));
    x2 = fmaf(a1.x,v20, fmaf(a1.y,v21, fmaf(a1.z,v22, fmaf(a1.w,v23, x2))));
    // node 1 dots (independent chains)
    float y0 = fmaf(c0.x,w00, fmaf(c0.y,w01, fmaf(c0.z,w02, c0.w*w03)));
    float y1 = fmaf(c0.x,w10, fmaf(c0.y,w11, fmaf(c0.z,w12, c0.w*w13)));
    float y2 = fmaf(c0.x,w20, fmaf(c0.y,w21, fmaf(c0.z,w22, c0.w*w23)));
    y0 = fmaf(c1.x,v00, fmaf(c1.y,v01, fmaf(c1.z,v02, fmaf(c1.w,v03, y0))));
    y1 = fmaf(c1.x,v10, fmaf(c1.y,v11, fmaf(c1.z,v12, fmaf(c1.w,v13, y1))));
    y2 = fmaf(c1.x,v20, fmaf(c1.y,v21, fmaf(c1.z,v22, fmaf(c1.w,v23, y2))));

    const unsigned full = 0xffffffffu;
    #pragma unroll
    for (int off = 16; off > 0; off >>= 1) {
        x0 += __shfl_down_sync(full, x0, off);
        x1 += __shfl_down_sync(full, x1, off);
        x2 += __shfl_down_sync(full, x2, off);
        y0 += __shfl_down_sync(full, y0, off);
        y1 += __shfl_down_sync(full, y1, off);
        y2 += __shfl_down_sync(full, y2, off);
    }
    if (lane == 0) {
        float4 zv = make_float4(x0, x1, x2, 1.0f);
        g_z[w0]   = zv;
        g_acc[w0] = zv;
        if (h1) {
            float4 yv = make_float4(y0, y1, y2, 1.0f);
            g_z[w1]   = yv;
            g_acc[w1] = yv;
        }
    }
    pdl_trigger();
}

// ---------------------------------------------------------------------------
// Kernel 2: edge aggregation. FOUR edges per thread (int4 index loads,
// 4 independent z reads + 4 REDG v4 in flight).
// ---------------------------------------------------------------------------
__global__ void k_edge(const int* __restrict__ src,
                       const int* __restrict__ dst, int E) {
    int q  = blockIdx.x * blockDim.x + threadIdx.x;
    int e0 = q * 4;
    if (e0 >= E) { pdl_wait(); pdl_trigger(); return; }

    if (e0 + 3 < E) {
        int4 sv = __ldg(reinterpret_cast<const int4*>(src) + q);
        int4 dv = __ldg(reinterpret_cast<const int4*>(dst) + q);
        pdl_wait();   // g_z / g_acc ready
        float4 v0 = __ldg(&g_z[sv.x]);
        float4 v1 = __ldg(&g_z[sv.y]);
        float4 v2 = __ldg(&g_z[sv.z]);
        float4 v3 = __ldg(&g_z[sv.w]);
        redg_v4(&g_acc[dv.x], v0);
        redg_v4(&g_acc[dv.y], v1);
        redg_v4(&g_acc[dv.z], v2);
        redg_v4(&g_acc[dv.w], v3);
    } else {
        pdl_wait();
        for (int e = e0; e < E; e++) {
            int s = __ldg(&src[e]);
            int d = __ldg(&dst[e]);
            redg_v4(&g_acc[d], __ldg(&g_z[s]));
        }
    }
    pdl_trigger();
}

// ---------------------------------------------------------------------------
// Kernel 3: finalize. Two nodes per thread (independent chains).
// ---------------------------------------------------------------------------
__global__ void k_final(float* __restrict__ out, int N) {
    int p  = blockIdx.x * blockDim.x + threadIdx.x;
    int i0 = p * 2;
    pdl_wait();   // all REDG from k_edge visible
    if (i0 >= N) return;
    int i1 = i0 + 1;
    bool has1 = (i1 < N);

    float4 a = g_acc[i0];
    float4 b = has1 ? g_acc[i1] : make_float4(0.f, 0.f, 0.f, 1.f);
    float bc0 = g_bc[0], bc1 = g_bc[1], bc2 = g_bc[2];

    float inva = __frcp_rn(a.w);
    float invb = __frcp_rn(b.w);
    float as0 = fmaf(a.x, inva, bc0), bs0 = fmaf(b.x, invb, bc0);
    float as1 = fmaf(a.y, inva, bc1), bs1 = fmaf(b.y, invb, bc1);
    float as2 = fmaf(a.z, inva, bc2), bs2 = fmaf(b.z, invb, bc2);

    float am = fmaxf(as0, fmaxf(as1, as2));
    float bm = fmaxf(bs0, fmaxf(bs1, bs2));
    float ae0 = __expf(as0 - am), be0 = __expf(bs0 - bm);
    float ae1 = __expf(as1 - am), be1 = __expf(bs1 - bm);
    float ae2 = __expf(as2 - am), be2 = __expf(bs2 - bm);
    float alse = am + __logf(ae0 + ae1 + ae2);
    float blse = bm + __logf(be0 + be1 + be2);

    out[i0 * 3 + 0] = as0 - alse;
    out[i0 * 3 + 1] = as1 - alse;
    out[i0 * 3 + 2] = as2 - alse;
    if (has1) {
        out[i1 * 3 + 0] = bs0 - blse;
        out[i1 * 3 + 1] = bs1 - blse;
        out[i1 * 3 + 2] = bs2 - blse;
    }
}

// ---------------------------------------------------------------------------
static inline void launch_pdl(void* fn, dim3 grid, dim3 block,
                              void** args, bool pdl_in) {
    cudaLaunchConfig_t cfg = {};
    cfg.gridDim  = grid;
    cfg.blockDim = block;
    cfg.dynamicSmemBytes = 0;
    cfg.stream = 0;
    cudaLaunchAttribute attr[1];
    int nattr = 0;
    if (pdl_in) {
        attr[0].id = cudaLaunchAttributeProgrammaticStreamSerialization;
        attr[0].val.programmaticStreamSerializationAllowed = 1;
        nattr = 1;
    }
    cfg.attrs = attr;
    cfg.numAttrs = nattr;
    cudaLaunchKernelExC(&cfg, fn, args);
}

extern "C" void kernel_launch(void* const* d_in, const int* in_sizes, int n_in,
                              void* d_out, int out_size) {
    const float* x_all  = (const float*)d_in[0];
    const int*   n_id   = (const int*)  d_in[1];
    const int*   eidx   = (const int*)  d_in[2];
    const float* W_sage = (const float*)d_in[3];
    const float* b_sage = (const float*)d_in[4];
    const float* W_cls  = (const float*)d_in[5];
    const float* b_cls  = (const float*)d_in[6];
    float* out = (float*)d_out;

    int N = in_sizes[1];          // 50000
    int E = in_sizes[2] / 2;      // 300000
    const int* src = eidx;        // edge_index[0, :]
    const int* dst = eidx + E;    // edge_index[1, :]

    // k_init: 771 warp-tasks
    {
        int threads = (CCLS * FDIM + CCLS) * 32;
        dim3 g((threads + 255) / 256), b(256);
        void* args[] = {(void*)&W_sage, (void*)&b_sage, (void*)&W_cls, (void*)&b_cls};
        launch_pdl((void*)k_init, g, b, args, false);
    }
    // k_z: TWO nodes per warp
    {
        const float4* x4 = reinterpret_cast<const float4*>(x_all);
        int warps = (N + 1) / 2;
        long long th = (long long)warps * 32;
        dim3 g((unsigned)((th + 255) / 256)), b(256);
        void* args[] = {(void*)&x4, (void*)&n_id, (void*)&N};
        launch_pdl((void*)k_z, g, b, args, true);
    }
    // k_edge: four edges per thread
    {
        int quads = (E + 3) / 4;
        dim3 g((quads + 255) / 256), b(256);
        void* args[] = {(void*)&src, (void*)&dst, (void*)&E};
        launch_pdl((void*)k_edge, g, b, args, true);
    }
    // k_final: two nodes per thread, block=128
    {
        int pairs = (N + 1) / 2;
        dim3 g((pairs + 127) / 128), b(128);
        void* args[] = {(void*)&out, (void*)&N};
        launch_pdl((void*)k_final, g, b, args, true);
    }
}

// round 12
// speedup vs baseline: 1.2095x; 1.0015x over previous
#include <cuda_runtime.h>
#include <cuda_bf16.h>
#include <math.h>

// Shapes (fixed dataset):
//   x_all: [100000, 256] f32, n_id: [50000] i32, edge_index: [2, 300000] i32
//   W_sage: [256,256] f32, b_sage: [256] f32, W_cls: [3,256] f32, b_cls: [3] f32
//   out: [50000, 3] f32 (log_softmax)
//
// out = log_softmax( mean_j( x[j] @ Wc ) + bc )  (linearity)
// 4-kernel PDL pipeline: k_init -> k_z -> k_edge -> k_final
// R12 change: k_z does FOUR nodes per warp (8 independent LDG.128/lane).
#define NMAX 50000
#define FDIM 256
#define F4   64
#define CCLS 3

__device__ float  g_Wc [CCLS * FDIM];
__device__ float  g_bc [CCLS];
__device__ float4 g_z  [NMAX];
__device__ float4 g_acc[NMAX];

__device__ __forceinline__ void pdl_wait()    { asm volatile("griddepcontrol.wait;" ::: "memory"); }
__device__ __forceinline__ void pdl_trigger() { asm volatile("griddepcontrol.launch_dependents;" ::: "memory"); }
__device__ __forceinline__ void redg_v4(float4* p, float4 v) {
    asm volatile("red.global.add.v4.f32 [%0], {%1, %2, %3, %4};"
                 :: "l"(p), "f"(v.x), "f"(v.y), "f"(v.z), "f"(v.w) : "memory");
}

// ---------------------------------------------------------------------------
// Kernel 0: parallel weight fusion. One warp per output element.
// ---------------------------------------------------------------------------
__global__ void k_init(const float* __restrict__ W_sage,
                       const float* __restrict__ b_sage,
                       const float* __restrict__ W_cls,
                       const float* __restrict__ b_cls) {
    int gid  = blockIdx.x * blockDim.x + threadIdx.x;
    int ww   = gid >> 5;
    int lane = gid & 31;
    const unsigned full = 0xffffffffu;

    if (ww < CCLS * FDIM) {
        int c = ww >> 8;
        int k = ww & 255;
        const float4* wrow = reinterpret_cast<const float4*>(W_sage + k * FDIM);
        const float4* crow = reinterpret_cast<const float4*>(W_cls  + c * FDIM);
        float4 a0 = __ldg(&wrow[lane]);      float4 b0 = __ldg(&crow[lane]);
        float4 a1 = __ldg(&wrow[lane + 32]); float4 b1 = __ldg(&crow[lane + 32]);
        float s = fmaf(a0.x, b0.x, fmaf(a0.y, b0.y, fmaf(a0.z, b0.z, a0.w * b0.w)))
                + fmaf(a1.x, b1.x, fmaf(a1.y, b1.y, fmaf(a1.z, b1.z, a1.w * b1.w)));
        #pragma unroll
        for (int off = 16; off > 0; off >>= 1)
            s += __shfl_down_sync(full, s, off);
        if (lane == 0) g_Wc[c * FDIM + k] = s;
    } else if (ww < CCLS * FDIM + CCLS) {
        int c = ww - CCLS * FDIM;
        const float4* brow = reinterpret_cast<const float4*>(b_sage);
        const float4* crow = reinterpret_cast<const float4*>(W_cls + c * FDIM);
        float4 a0 = __ldg(&brow[lane]);      float4 b0 = __ldg(&crow[lane]);
        float4 a1 = __ldg(&brow[lane + 32]); float4 b1 = __ldg(&crow[lane + 32]);
        float s = fmaf(a0.x, b0.x, fmaf(a0.y, b0.y, fmaf(a0.z, b0.z, a0.w * b0.w)))
                + fmaf(a1.x, b1.x, fmaf(a1.y, b1.y, fmaf(a1.z, b1.z, a1.w * b1.w)));
        #pragma unroll
        for (int off = 16; off > 0; off >>= 1)
            s += __shfl_down_sync(full, s, off);
        if (lane == 0) g_bc[c] = s + __ldg(&b_cls[c]);
    }
    pdl_trigger();
}

// ---------------------------------------------------------------------------
// Kernel 1: project, FOUR nodes per warp.
//   z[i] = x_all[n_id[i]] @ Wc, .w = 1;  acc[i] = z[i]  (self loop)
// All 8 row LDG.128 per lane are PRE-wait prologue (independent of g_Wc).
// ---------------------------------------------------------------------------
__global__ void k_z(const float4* __restrict__ x_all4,
                    const int* __restrict__ n_id, int N) {
    __shared__ float sW[CCLS][FDIM];
    int t    = threadIdx.x;
    int wp   = (blockIdx.x * blockDim.x + t) >> 5;   // warp id
    int lane = t & 31;
    int w0 = wp * 4;

    float4 d0a, d0b, d1a, d1b, d2a, d2b, d3a, d3b;
    const float4 Z = make_float4(0.f, 0.f, 0.f, 0.f);
    d0a = d0b = d1a = d1b = d2a = d2b = d3a = d3b = Z;
    bool h0 = (w0     < N);
    bool h1 = (w0 + 1 < N);
    bool h2 = (w0 + 2 < N);
    bool h3 = (w0 + 3 < N);
    if (h0) {
        const float4* xp = x_all4 + (long long)__ldg(&n_id[w0]) * F4;
        d0a = __ldg(&xp[lane]); d0b = __ldg(&xp[lane + 32]);
    }
    if (h1) {
        const float4* xp = x_all4 + (long long)__ldg(&n_id[w0 + 1]) * F4;
        d1a = __ldg(&xp[lane]); d1b = __ldg(&xp[lane + 32]);
    }
    if (h2) {
        const float4* xp = x_all4 + (long long)__ldg(&n_id[w0 + 2]) * F4;
        d2a = __ldg(&xp[lane]); d2b = __ldg(&xp[lane + 32]);
    }
    if (h3) {
        const float4* xp = x_all4 + (long long)__ldg(&n_id[w0 + 3]) * F4;
        d3a = __ldg(&xp[lane]); d3b = __ldg(&xp[lane + 32]);
    }

    pdl_wait();   // g_Wc ready
    for (int idx = t; idx < CCLS * FDIM; idx += blockDim.x)
        sW[idx >> 8][idx & 255] = g_Wc[idx];
    __syncthreads();

    if (!h0) { pdl_trigger(); return; }

    int k0 = lane * 4, k1 = (lane + 32) * 4;
    float w00 = sW[0][k0], w01 = sW[0][k0+1], w02 = sW[0][k0+2], w03 = sW[0][k0+3];
    float w10 = sW[1][k0], w11 = sW[1][k0+1], w12 = sW[1][k0+2], w13 = sW[1][k0+3];
    float w20 = sW[2][k0], w21 = sW[2][k0+1], w22 = sW[2][k0+2], w23 = sW[2][k0+3];
    float v00 = sW[0][k1], v01 = sW[0][k1+1], v02 = sW[0][k1+2], v03 = sW[0][k1+3];
    float v10 = sW[1][k1], v11 = sW[1][k1+1], v12 = sW[1][k1+2], v13 = sW[1][k1+3];
    float v20 = sW[2][k1], v21 = sW[2][k1+1], v22 = sW[2][k1+2], v23 = sW[2][k1+3];

    #define DOT3(ra, rb, o0, o1, o2)                                            \
        o0 = fmaf((ra).x,w00, fmaf((ra).y,w01, fmaf((ra).z,w02, (ra).w*w03)));  \
        o1 = fmaf((ra).x,w10, fmaf((ra).y,w11, fmaf((ra).z,w12, (ra).w*w13)));  \
        o2 = fmaf((ra).x,w20, fmaf((ra).y,w21, fmaf((ra).z,w22, (ra).w*w23)));  \
        o0 = fmaf((rb).x,v00, fmaf((rb).y,v01, fmaf((rb).z,v02, fmaf((rb).w,v03, o0)))); \
        o1 = fmaf((rb).x,v10, fmaf((rb).y,v11, fmaf((rb).z,v12, fmaf((rb).w,v13, o1)))); \
        o2 = fmaf((rb).x,v20, fmaf((rb).y,v21, fmaf((rb).z,v22, fmaf((rb).w,v23, o2))));

    float x0, x1, x2, y0, y1, y2, u0, u1, u2, q0, q1, q2;
    DOT3(d0a, d0b, x0, x1, x2)
    DOT3(d1a, d1b, y0, y1, y2)
    DOT3(d2a, d2b, u0, u1, u2)
    DOT3(d3a, d3b, q0, q1, q2)
    #undef DOT3

    const unsigned full = 0xffffffffu;
    #pragma unroll
    for (int off = 16; off > 0; off >>= 1) {
        x0 += __shfl_down_sync(full, x0, off);
        x1 += __shfl_down_sync(full, x1, off);
        x2 += __shfl_down_sync(full, x2, off);
        y0 += __shfl_down_sync(full, y0, off);
        y1 += __shfl_down_sync(full, y1, off);
        y2 += __shfl_down_sync(full, y2, off);
        u0 += __shfl_down_sync(full, u0, off);
        u1 += __shfl_down_sync(full, u1, off);
        u2 += __shfl_down_sync(full, u2, off);
        q0 += __shfl_down_sync(full, q0, off);
        q1 += __shfl_down_sync(full, q1, off);
        q2 += __shfl_down_sync(full, q2, off);
    }
    if (lane == 0) {
        float4 zv = make_float4(x0, x1, x2, 1.0f);
        g_z[w0] = zv;  g_acc[w0] = zv;
        if (h1) { float4 v = make_float4(y0, y1, y2, 1.0f); g_z[w0+1] = v; g_acc[w0+1] = v; }
        if (h2) { float4 v = make_float4(u0, u1, u2, 1.0f); g_z[w0+2] = v; g_acc[w0+2] = v; }
        if (h3) { float4 v = make_float4(q0, q1, q2, 1.0f); g_z[w0+3] = v; g_acc[w0+3] = v; }
    }
    pdl_trigger();
}

// ---------------------------------------------------------------------------
// Kernel 2: edge aggregation. FOUR edges per thread (int4 index loads,
// 4 independent z reads + 4 REDG v4 in flight).
// ---------------------------------------------------------------------------
__global__ void k_edge(const int* __restrict__ src,
                       const int* __restrict__ dst, int E) {
    int q  = blockIdx.x * blockDim.x + threadIdx.x;
    int e0 = q * 4;
    if (e0 >= E) { pdl_wait(); pdl_trigger(); return; }

    if (e0 + 3 < E) {
        int4 sv = __ldg(reinterpret_cast<const int4*>(src) + q);
        int4 dv = __ldg(reinterpret_cast<const int4*>(dst) + q);
        pdl_wait();   // g_z / g_acc ready
        float4 v0 = __ldg(&g_z[sv.x]);
        float4 v1 = __ldg(&g_z[sv.y]);
        float4 v2 = __ldg(&g_z[sv.z]);
        float4 v3 = __ldg(&g_z[sv.w]);
        redg_v4(&g_acc[dv.x], v0);
        redg_v4(&g_acc[dv.y], v1);
        redg_v4(&g_acc[dv.z], v2);
        redg_v4(&g_acc[dv.w], v3);
    } else {
        pdl_wait();
        for (int e = e0; e < E; e++) {
            int s = __ldg(&src[e]);
            int d = __ldg(&dst[e]);
            redg_v4(&g_acc[d], __ldg(&g_z[s]));
        }
    }
    pdl_trigger();
}

// ---------------------------------------------------------------------------
// Kernel 3: finalize. Two nodes per thread (independent chains).
// ---------------------------------------------------------------------------
__global__ void k_final(float* __restrict__ out, int N) {
    int p  = blockIdx.x * blockDim.x + threadIdx.x;
    int i0 = p * 2;
    pdl_wait();   // all REDG from k_edge visible
    if (i0 >= N) return;
    int i1 = i0 + 1;
    bool has1 = (i1 < N);

    float4 a = g_acc[i0];
    float4 b = has1 ? g_acc[i1] : make_float4(0.f, 0.f, 0.f, 1.f);
    float bc0 = g_bc[0], bc1 = g_bc[1], bc2 = g_bc[2];

    float inva = __frcp_rn(a.w);
    float invb = __frcp_rn(b.w);
    float as0 = fmaf(a.x, inva, bc0), bs0 = fmaf(b.x, invb, bc0);
    float as1 = fmaf(a.y, inva, bc1), bs1 = fmaf(b.y, invb, bc1);
    float as2 = fmaf(a.z, inva, bc2), bs2 = fmaf(b.z, invb, bc2);

    float am = fmaxf(as0, fmaxf(as1, as2));
    float bm = fmaxf(bs0, fmaxf(bs1, bs2));
    float ae0 = __expf(as0 - am), be0 = __expf(bs0 - bm);
    float ae1 = __expf(as1 - am), be1 = __expf(bs1 - bm);
    float ae2 = __expf(as2 - am), be2 = __expf(bs2 - bm);
    float alse = am + __logf(ae0 + ae1 + ae2);
    float blse = bm + __logf(be0 + be1 + be2);

    out[i0 * 3 + 0] = as0 - alse;
    out[i0 * 3 + 1] = as1 - alse;
    out[i0 * 3 + 2] = as2 - alse;
    if (has1) {
        out[i1 * 3 + 0] = bs0 - blse;
        out[i1 * 3 + 1] = bs1 - blse;
        out[i1 * 3 + 2] = bs2 - blse;
    }
}

// ---------------------------------------------------------------------------
static inline void launch_pdl(void* fn, dim3 grid, dim3 block,
                              void** args, bool pdl_in) {
    cudaLaunchConfig_t cfg = {};
    cfg.gridDim  = grid;
    cfg.blockDim = block;
    cfg.dynamicSmemBytes = 0;
    cfg.stream = 0;
    cudaLaunchAttribute attr[1];
    int nattr = 0;
    if (pdl_in) {
        attr[0].id = cudaLaunchAttributeProgrammaticStreamSerialization;
        attr[0].val.programmaticStreamSerializationAllowed = 1;
        nattr = 1;
    }
    cfg.attrs = attr;
    cfg.numAttrs = nattr;
    cudaLaunchKernelExC(&cfg, fn, args);
}

extern "C" void kernel_launch(void* const* d_in, const int* in_sizes, int n_in,
                              void* d_out, int out_size) {
    const float* x_all  = (const float*)d_in[0];
    const int*   n_id   = (const int*)  d_in[1];
    const int*   eidx   = (const int*)  d_in[2];
    const float* W_sage = (const float*)d_in[3];
    const float* b_sage = (const float*)d_in[4];
    const float* W_cls  = (const float*)d_in[5];
    const float* b_cls  = (const float*)d_in[6];
    float* out = (float*)d_out;

    int N = in_sizes[1];          // 50000
    int E = in_sizes[2] / 2;      // 300000
    const int* src = eidx;        // edge_index[0, :]
    const int* dst = eidx + E;    // edge_index[1, :]

    // k_init: 771 warp-tasks
    {
        int threads = (CCLS * FDIM + CCLS) * 32;
        dim3 g((threads + 255) / 256), b(256);
        void* args[] = {(void*)&W_sage, (void*)&b_sage, (void*)&W_cls, (void*)&b_cls};
        launch_pdl((void*)k_init, g, b, args, false);
    }
    // k_z: FOUR nodes per warp
    {
        const float4* x4 = reinterpret_cast<const float4*>(x_all);
        int warps = (N + 3) / 4;
        long long th = (long long)warps * 32;
        dim3 g((unsigned)((th + 255) / 256)), b(256);
        void* args[] = {(void*)&x4, (void*)&n_id, (void*)&N};
        launch_pdl((void*)k_z, g, b, args, true);
    }
    // k_edge: four edges per thread
    {
        int quads = (E + 3) / 4;
        dim3 g((quads + 255) / 256), b(256);
        void* args[] = {(void*)&src, (void*)&dst, (void*)&E};
        launch_pdl((void*)k_edge, g, b, args, true);
    }
    // k_final: two nodes per thread, block=128
    {
        int pairs = (N + 1) / 2;
        dim3 g((pairs + 127) / 128), b(128);
        void* args[] = {(void*)&out, (void*)&N};
        launch_pdl((void*)k_final, g, b, args, true);
    }
}

// round 13
// speedup vs baseline: 1.3316x; 1.1010x over previous
#include <cuda_runtime.h>
#include <cuda_bf16.h>
#include <math.h>

// Shapes (fixed dataset):
//   x_all: [100000, 256] f32, n_id: [50000] i32, edge_index: [2, 300000] i32
//   W_sage: [256,256] f32, b_sage: [256] f32, W_cls: [3,256] f32, b_cls: [3] f32
//   out: [50000, 3] f32 (log_softmax)
//
// out = log_softmax( mean_j( x[j] @ Wc ) + bc )  (linearity)
// log_softmax is shift-invariant -> only score DIFFERENCES vs class 2 matter:
//   d_c = row @ (Wc_c - Wc_2),  g_c = mean(d_c) + (bc_c - bc_2),  c in {0,1}
//   out2 = -log(e^g0 + e^g1 + 1);  out_c = g_c + out2
// => project to 2 floats/node; edge aggregation = REDG.v2 + scalar count
//    (3 atomic lanes/edge instead of 4).
// 4-kernel PDL pipeline: k_init -> k_z -> k_edge -> k_final
#define NMAX 50000
#define FDIM 256
#define F4   64
#define CCLS 2          // two difference classes

__device__ float  g_Wd  [CCLS * FDIM];   // diff weights (Wc_c - Wc_2 folded)
__device__ float  g_bd  [CCLS];          // diff biases
__device__ float2 g_z   [NMAX];          // per-node projected diffs
__device__ float2 g_accd[NMAX];          // accumulated diffs
__device__ float  g_cnt [NMAX];          // neighbor count incl. self

__device__ __forceinline__ void pdl_wait()    { asm volatile("griddepcontrol.wait;" ::: "memory"); }
__device__ __forceinline__ void pdl_trigger() { asm volatile("griddepcontrol.launch_dependents;" ::: "memory"); }
__device__ __forceinline__ void redg_v2(float2* p, float2 v) {
    asm volatile("red.global.add.v2.f32 [%0], {%1, %2};"
                 :: "l"(p), "f"(v.x), "f"(v.y) : "memory");
}
__device__ __forceinline__ void redg_f32(float* p, float v) {
    asm volatile("red.global.add.f32 [%0], %1;"
                 :: "l"(p), "f"(v) : "memory");
}

// ---------------------------------------------------------------------------
// Kernel 0: parallel fusion of diff weights. One warp per output element.
//   Wd[c][k] = sum_h W_sage[k,h] * (W_cls[c,h] - W_cls[2,h])   c in {0,1}
//   bd[c]    = sum_h b_sage[h]   * (W_cls[c,h] - W_cls[2,h]) + b_cls[c]-b_cls[2]
// ---------------------------------------------------------------------------
__global__ void k_init(const float* __restrict__ W_sage,
                       const float* __restrict__ b_sage,
                       const float* __restrict__ W_cls,
                       const float* __restrict__ b_cls) {
    int gid  = blockIdx.x * blockDim.x + threadIdx.x;
    int ww   = gid >> 5;
    int lane = gid & 31;
    const unsigned full = 0xffffffffu;

    if (ww < CCLS * FDIM) {
        int c = ww >> 8;          // 0 or 1
        int k = ww & 255;
        const float4* wrow = reinterpret_cast<const float4*>(W_sage + k * FDIM);
        const float4* crow = reinterpret_cast<const float4*>(W_cls  + c * FDIM);
        const float4* rrow = reinterpret_cast<const float4*>(W_cls  + 2 * FDIM);
        float4 a0 = __ldg(&wrow[lane]);      float4 a1 = __ldg(&wrow[lane + 32]);
        float4 b0 = __ldg(&crow[lane]);      float4 b1 = __ldg(&crow[lane + 32]);
        float4 r0 = __ldg(&rrow[lane]);      float4 r1 = __ldg(&rrow[lane + 32]);
        float4 e0 = make_float4(b0.x-r0.x, b0.y-r0.y, b0.z-r0.z, b0.w-r0.w);
        float4 e1 = make_float4(b1.x-r1.x, b1.y-r1.y, b1.z-r1.z, b1.w-r1.w);
        float s = fmaf(a0.x, e0.x, fmaf(a0.y, e0.y, fmaf(a0.z, e0.z, a0.w * e0.w)))
                + fmaf(a1.x, e1.x, fmaf(a1.y, e1.y, fmaf(a1.z, e1.z, a1.w * e1.w)));
        #pragma unroll
        for (int off = 16; off > 0; off >>= 1)
            s += __shfl_down_sync(full, s, off);
        if (lane == 0) g_Wd[c * FDIM + k] = s;
    } else if (ww < CCLS * FDIM + CCLS) {
        int c = ww - CCLS * FDIM;
        const float4* brow = reinterpret_cast<const float4*>(b_sage);
        const float4* crow = reinterpret_cast<const float4*>(W_cls + c * FDIM);
        const float4* rrow = reinterpret_cast<const float4*>(W_cls + 2 * FDIM);
        float4 a0 = __ldg(&brow[lane]);      float4 a1 = __ldg(&brow[lane + 32]);
        float4 b0 = __ldg(&crow[lane]);      float4 b1 = __ldg(&crow[lane + 32]);
        float4 r0 = __ldg(&rrow[lane]);      float4 r1 = __ldg(&rrow[lane + 32]);
        float4 e0 = make_float4(b0.x-r0.x, b0.y-r0.y, b0.z-r0.z, b0.w-r0.w);
        float4 e1 = make_float4(b1.x-r1.x, b1.y-r1.y, b1.z-r1.z, b1.w-r1.w);
        float s = fmaf(a0.x, e0.x, fmaf(a0.y, e0.y, fmaf(a0.z, e0.z, a0.w * e0.w)))
                + fmaf(a1.x, e1.x, fmaf(a1.y, e1.y, fmaf(a1.z, e1.z, a1.w * e1.w)));
        #pragma unroll
        for (int off = 16; off > 0; off >>= 1)
            s += __shfl_down_sync(full, s, off);
        if (lane == 0) g_bd[c] = s + __ldg(&b_cls[c]) - __ldg(&b_cls[2]);
    }
    pdl_trigger();
}

// ---------------------------------------------------------------------------
// Kernel 1: project, FOUR nodes per warp (8 independent LDG.128/lane pre-wait).
//   z[i] = x_all[n_id[i]] @ Wd (2 floats);  accd[i] = z[i]; cnt[i] = 1
// ---------------------------------------------------------------------------
__global__ void k_z(const float4* __restrict__ x_all4,
                    const int* __restrict__ n_id, int N) {
    __shared__ float sW[CCLS][FDIM];
    int t    = threadIdx.x;
    int wp   = (blockIdx.x * blockDim.x + t) >> 5;
    int lane = t & 31;
    int w0 = wp * 4;

    float4 d0a, d0b, d1a, d1b, d2a, d2b, d3a, d3b;
    const float4 Z = make_float4(0.f, 0.f, 0.f, 0.f);
    d0a = d0b = d1a = d1b = d2a = d2b = d3a = d3b = Z;
    bool h0 = (w0     < N);
    bool h1 = (w0 + 1 < N);
    bool h2 = (w0 + 2 < N);
    bool h3 = (w0 + 3 < N);
    if (h0) {
        const float4* xp = x_all4 + (long long)__ldg(&n_id[w0]) * F4;
        d0a = __ldg(&xp[lane]); d0b = __ldg(&xp[lane + 32]);
    }
    if (h1) {
        const float4* xp = x_all4 + (long long)__ldg(&n_id[w0 + 1]) * F4;
        d1a = __ldg(&xp[lane]); d1b = __ldg(&xp[lane + 32]);
    }
    if (h2) {
        const float4* xp = x_all4 + (long long)__ldg(&n_id[w0 + 2]) * F4;
        d2a = __ldg(&xp[lane]); d2b = __ldg(&xp[lane + 32]);
    }
    if (h3) {
        const float4* xp = x_all4 + (long long)__ldg(&n_id[w0 + 3]) * F4;
        d3a = __ldg(&xp[lane]); d3b = __ldg(&xp[lane + 32]);
    }

    pdl_wait();   // g_Wd ready
    for (int idx = t; idx < CCLS * FDIM; idx += blockDim.x)
        sW[idx >> 8][idx & 255] = g_Wd[idx];
    __syncthreads();

    if (!h0) { pdl_trigger(); return; }

    int k0 = lane * 4, k1 = (lane + 32) * 4;
    float w00 = sW[0][k0], w01 = sW[0][k0+1], w02 = sW[0][k0+2], w03 = sW[0][k0+3];
    float w10 = sW[1][k0], w11 = sW[1][k0+1], w12 = sW[1][k0+2], w13 = sW[1][k0+3];
    float v00 = sW[0][k1], v01 = sW[0][k1+1], v02 = sW[0][k1+2], v03 = sW[0][k1+3];
    float v10 = sW[1][k1], v11 = sW[1][k1+1], v12 = sW[1][k1+2], v13 = sW[1][k1+3];

    #define DOT2(ra, rb, o0, o1)                                                \
        o0 = fmaf((ra).x,w00, fmaf((ra).y,w01, fmaf((ra).z,w02, (ra).w*w03)));  \
        o1 = fmaf((ra).x,w10, fmaf((ra).y,w11, fmaf((ra).z,w12, (ra).w*w13)));  \
        o0 = fmaf((rb).x,v00, fmaf((rb).y,v01, fmaf((rb).z,v02, fmaf((rb).w,v03, o0)))); \
        o1 = fmaf((rb).x,v10, fmaf((rb).y,v11, fmaf((rb).z,v12, fmaf((rb).w,v13, o1))));

    float x0, x1, y0, y1, u0, u1, q0, q1;
    DOT2(d0a, d0b, x0, x1)
    DOT2(d1a, d1b, y0, y1)
    DOT2(d2a, d2b, u0, u1)
    DOT2(d3a, d3b, q0, q1)
    #undef DOT2

    const unsigned full = 0xffffffffu;
    #pragma unroll
    for (int off = 16; off > 0; off >>= 1) {
        x0 += __shfl_down_sync(full, x0, off);
        x1 += __shfl_down_sync(full, x1, off);
        y0 += __shfl_down_sync(full, y0, off);
        y1 += __shfl_down_sync(full, y1, off);
        u0 += __shfl_down_sync(full, u0, off);
        u1 += __shfl_down_sync(full, u1, off);
        q0 += __shfl_down_sync(full, q0, off);
        q1 += __shfl_down_sync(full, q1, off);
    }
    if (lane == 0) {
        float2 zv = make_float2(x0, x1);
        g_z[w0] = zv;  g_accd[w0] = zv;  g_cnt[w0] = 1.0f;
        if (h1) { float2 v = make_float2(y0, y1); g_z[w0+1] = v; g_accd[w0+1] = v; g_cnt[w0+1] = 1.0f; }
        if (h2) { float2 v = make_float2(u0, u1); g_z[w0+2] = v; g_accd[w0+2] = v; g_cnt[w0+2] = 1.0f; }
        if (h3) { float2 v = make_float2(q0, q1); g_z[w0+3] = v; g_accd[w0+3] = v; g_cnt[w0+3] = 1.0f; }
    }
    pdl_trigger();
}

// ---------------------------------------------------------------------------
// Kernel 2: edge aggregation. FOUR edges per thread.
//   accd[dst] += z[src]  (REDG v2, 2 lanes) ;  cnt[dst] += 1  (REDG f32, 1 lane)
// 3 atomic lanes/edge instead of 4.
// ---------------------------------------------------------------------------
__global__ void k_edge(const int* __restrict__ src,
                       const int* __restrict__ dst, int E) {
    int q  = blockIdx.x * blockDim.x + threadIdx.x;
    int e0 = q * 4;
    if (e0 >= E) { pdl_wait(); pdl_trigger(); return; }

    if (e0 + 3 < E) {
        int4 sv = __ldg(reinterpret_cast<const int4*>(src) + q);
        int4 dv = __ldg(reinterpret_cast<const int4*>(dst) + q);
        pdl_wait();   // g_z / g_accd / g_cnt ready
        float2 v0 = __ldg(&g_z[sv.x]);
        float2 v1 = __ldg(&g_z[sv.y]);
        float2 v2 = __ldg(&g_z[sv.z]);
        float2 v3 = __ldg(&g_z[sv.w]);
        redg_v2(&g_accd[dv.x], v0);
        redg_v2(&g_accd[dv.y], v1);
        redg_v2(&g_accd[dv.z], v2);
        redg_v2(&g_accd[dv.w], v3);
        redg_f32(&g_cnt[dv.x], 1.0f);
        redg_f32(&g_cnt[dv.y], 1.0f);
        redg_f32(&g_cnt[dv.z], 1.0f);
        redg_f32(&g_cnt[dv.w], 1.0f);
    } else {
        pdl_wait();
        for (int e = e0; e < E; e++) {
            int s = __ldg(&src[e]);
            int d = __ldg(&dst[e]);
            redg_v2(&g_accd[d], __ldg(&g_z[s]));
            redg_f32(&g_cnt[d], 1.0f);
        }
    }
    pdl_trigger();
}

// ---------------------------------------------------------------------------
// Kernel 3: finalize. Two nodes per thread.
//   g_c = accd_c/cnt + bd_c ;  out2 = -lse(g0,g1,0);  out_c = g_c + out2
// ---------------------------------------------------------------------------
__global__ void k_final(float* __restrict__ out, int N) {
    int p  = blockIdx.x * blockDim.x + threadIdx.x;
    int i0 = p * 2;
    pdl_wait();   // all REDG visible
    if (i0 >= N) return;
    int i1 = i0 + 1;
    bool has1 = (i1 < N);

    float2 a  = g_accd[i0];
    float  ac = g_cnt[i0];
    float2 b  = has1 ? g_accd[i1] : make_float2(0.f, 0.f);
    float  bcnt = has1 ? g_cnt[i1] : 1.0f;
    float bd0 = g_bd[0], bd1 = g_bd[1];

    float inva = __frcp_rn(ac);
    float invb = __frcp_rn(bcnt);
    float ag0 = fmaf(a.x, inva, bd0), bg0 = fmaf(b.x, invb, bd0);
    float ag1 = fmaf(a.y, inva, bd1), bg1 = fmaf(b.y, invb, bd1);

    float am = fmaxf(0.0f, fmaxf(ag0, ag1));
    float bm = fmaxf(0.0f, fmaxf(bg0, bg1));
    float alse = am + __logf(__expf(ag0 - am) + __expf(ag1 - am) + __expf(-am));
    float blse = bm + __logf(__expf(bg0 - bm) + __expf(bg1 - bm) + __expf(-bm));

    out[i0 * 3 + 0] = ag0 - alse;
    out[i0 * 3 + 1] = ag1 - alse;
    out[i0 * 3 + 2] = -alse;
    if (has1) {
        out[i1 * 3 + 0] = bg0 - blse;
        out[i1 * 3 + 1] = bg1 - blse;
        out[i1 * 3 + 2] = -blse;
    }
}

// ---------------------------------------------------------------------------
static inline void launch_pdl(void* fn, dim3 grid, dim3 block,
                              void** args, bool pdl_in) {
    cudaLaunchConfig_t cfg = {};
    cfg.gridDim  = grid;
    cfg.blockDim = block;
    cfg.dynamicSmemBytes = 0;
    cfg.stream = 0;
    cudaLaunchAttribute attr[1];
    int nattr = 0;
    if (pdl_in) {
        attr[0].id = cudaLaunchAttributeProgrammaticStreamSerialization;
        attr[0].val.programmaticStreamSerializationAllowed = 1;
        nattr = 1;
    }
    cfg.attrs = attr;
    cfg.numAttrs = nattr;
    cudaLaunchKernelExC(&cfg, fn, args);
}

extern "C" void kernel_launch(void* const* d_in, const int* in_sizes, int n_in,
                              void* d_out, int out_size) {
    const float* x_all  = (const float*)d_in[0];
    const int*   n_id   = (const int*)  d_in[1];
    const int*   eidx   = (const int*)  d_in[2];
    const float* W_sage = (const float*)d_in[3];
    const float* b_sage = (const float*)d_in[4];
    const float* W_cls  = (const float*)d_in[5];
    const float* b_cls  = (const float*)d_in[6];
    float* out = (float*)d_out;

    int N = in_sizes[1];          // 50000
    int E = in_sizes[2] / 2;      // 300000
    const int* src = eidx;        // edge_index[0, :]
    const int* dst = eidx + E;    // edge_index[1, :]

    // k_init: 514 warp-tasks
    {
        int threads = (CCLS * FDIM + CCLS) * 32;
        dim3 g((threads + 255) / 256), b(256);
        void* args[] = {(void*)&W_sage, (void*)&b_sage, (void*)&W_cls, (void*)&b_cls};
        launch_pdl((void*)k_init, g, b, args, false);
    }
    // k_z: FOUR nodes per warp
    {
        const float4* x4 = reinterpret_cast<const float4*>(x_all);
        int warps = (N + 3) / 4;
        long long th = (long long)warps * 32;
        dim3 g((unsigned)((th + 255) / 256)), b(256);
        void* args[] = {(void*)&x4, (void*)&n_id, (void*)&N};
        launch_pdl((void*)k_z, g, b, args, true);
    }
    // k_edge: four edges per thread
    {
        int quads = (E + 3) / 4;
        dim3 g((quads + 255) / 256), b(256);
        void* args[] = {(void*)&src, (void*)&dst, (void*)&E};
        launch_pdl((void*)k_edge, g, b, args, true);
    }
    // k_final: two nodes per thread, block=128
    {
        int pairs = (N + 1) / 2;
        dim3 g((pairs + 127) / 128), b(128);
        void* args[] = {(void*)&out, (void*)&N};
        launch_pdl((void*)k_final, g, b, args, true);
    }
}